// round 5
// baseline (speedup 1.0000x reference)
#include <cuda_runtime.h>

// DTW loss: 32 independent 1024x1024 wavefront DPs, fused with path-loss
// accumulation (W[i,j] = w(i,j) + W[argmin-pred]) -> no backtrack needed.
//
// R4: 4-warp pipeline, 256 rows (RR=8) per warp, one warp per SMSP.
// Chunked release/acquire handoff (SCH=32 diagonals) with nanosleep backoff;
// sentinel-padded targets remove all per-cell validity logic.

#define NN 1024
#define MM 1024
#define RR 8                 // rows per thread
#define TT 128               // threads per block
#define NWARP 4
#define BAND 256             // rows per warp
#define RING 2048
#define SCH 32               // diagonals per sync chunk

#define FINF (__int_as_float(0x7f800000))
#define SENT 1.0e18f

__device__ float g_partial[64];

static __forceinline__ __device__ float fsqrt_approx(float x) {
    float r;
    asm("sqrt.approx.f32 %0, %1;" : "=f"(r) : "f"(x));
    return r;
}
static __forceinline__ __device__ unsigned smem_u32(const void* p) {
    return (unsigned)__cvta_generic_to_shared(p);
}

// target array: logical j in [-PADF, MM-1+PADF], swizzled idx = u + u/4
#define PADF 255
#define STN  1920            // (255+1024+255+1)*1.25 = 1919 -> 1920
#define RING_F2 (3 * RING)   // warps 0..2 produce
#define SMEM_BYTES (RING_F2 * 8 + 2 * STN * 4 + 8 * 4)

__global__ void __launch_bounds__(TT, 1)
dtw_forward_kernel(const float* __restrict__ preds,
                   const float* __restrict__ targs,
                   const float* __restrict__ subcoef)
{
    extern __shared__ unsigned char smem_raw[];
    float2*   ring = (float2*)smem_raw;               // [3][RING]
    float*    sTx  = (float*)(ring + RING_F2);        // [STN] swizzled + padded
    float*    sTy  = sTx + STN;
    unsigned* cnt  = (unsigned*)(sTy + STN);          // progress counters

    const int b    = blockIdx.x;
    const int tid  = threadIdx.x;
    const int lane = tid & 31;
    const int warp = tid >> 5;

    const float* __restrict__ pb = preds + (size_t)b * NN * 4;
    const float* __restrict__ tb = targs + (size_t)b * MM * 4;

    // stage targets with sentinel pad; swizzle idx = u + u/4 (stride-5 words
    // -> conflict-free for the stride-RR lane access pattern)
    for (int u = tid; u < PADF + MM + PADF + 1; u += TT) {
        int j = u - PADF;
        int idx = u + (u >> 2);
        bool in = (unsigned)j < (unsigned)MM;
        int jc = in ? j : 0;
        sTx[idx] = in ? tb[jc * 4 + 0] : SENT;
        sTy[idx] = in ? tb[jc * 4 + 1] : SENT;
    }
    if (tid < NWARP) cnt[tid] = 0;

    const float s0 = subcoef[0];
    const float s1 = subcoef[1];

    const int i0 = tid * RR;
    float px[RR], py[RR];
#pragma unroll
    for (int r = 0; r < RR; ++r) {
        px[r] = pb[(i0 + r) * 4 + 0];
        py[r] = pb[(i0 + r) * 4 + 1];
    }

    float D1[RR], D2[RR], W1[RR], W2[RR];
#pragma unroll
    for (int r = 0; r < RR; ++r) { D1[r] = FINF; D2[r] = FINF; W1[r] = 0.f; W2[r] = 0.f; }

    // diag-(k-2) neighbor-row cache; warp0/lane0 seeds 0 for cell (0,0)
    float pD = (warp == 0 && lane == 0) ? 0.f : FINF;
    float pW = 0.f;

    const unsigned myCnt   = smem_u32(&cnt[warp]);
    const unsigned prevCnt = smem_u32(&cnt[warp > 0 ? warp - 1 : 0]);

    __syncthreads();

    const int kstart  = warp * BAND;
    const int kend    = kstart + BAND - 1 + MM - 1;
    const int pollend = kstart + MM - 1;

    // chunk-0 poll (uniform) + peel of ring[kstart-2] for pD
    if (warp > 0) {
        int need = kstart + SCH - 1;
        if (need > pollend) need = pollend;
        unsigned c;
        asm volatile("ld.acquire.cta.shared.u32 %0, [%1];" : "=r"(c) : "r"(prevCnt));
        while ((int)c < need) {
            __nanosleep(64);
            asm volatile("ld.acquire.cta.shared.u32 %0, [%1];" : "=r"(c) : "r"(prevCnt));
        }
        if (lane == 0) {
            float2 e = ring[(warp - 1) * RING + (kstart - 2)];
            pD = e.x; pW = e.y;
        }
    }

    // sliding target window: after the in-loop shift, tx[rr] = sT[j0 - rr]
    const int j0f = kstart - i0;
    float tx[RR], ty[RR];
#pragma unroll
    for (int q = 0; q < RR - 1; ++q) {
        int u = j0f - 1 - q + PADF;
        int ii = u + (u >> 2);
        tx[q] = sTx[ii]; ty[q] = sTy[ii];
    }
    tx[RR - 1] = SENT; ty[RR - 1] = SENT;

#pragma unroll 4
    for (int k = kstart; k <= kend; ++k) {
        const int rel = k - kstart;

        // per-chunk acquire poll (uniform, nanosleep backoff)
        if (warp > 0 && rel != 0 && (rel & (SCH - 1)) == 0 && k <= pollend) {
            int need = k + SCH - 1;
            if (need > pollend) need = pollend;
            unsigned c;
            asm volatile("ld.acquire.cta.shared.u32 %0, [%1];" : "=r"(c) : "r"(prevCnt));
            while ((int)c < need) {
                __nanosleep(64);
                asm volatile("ld.acquire.cta.shared.u32 %0, [%1];" : "=r"(c) : "r"(prevCnt));
            }
        }

        float nD1 = __shfl_up_sync(0xffffffffu, D1[RR - 1], 1);
        float nW1 = __shfl_up_sync(0xffffffffu, W1[RR - 1], 1);
        if (lane == 0) {
            if (warp == 0 || k > pollend) {
                nD1 = FINF; nW1 = 0.f;
            } else {
                float2 e = ring[(warp - 1) * RING + (k - 1)];
                nD1 = e.x; nW1 = e.y;
            }
        }
        const float nD2 = pD, nW2 = pW;
        pD = nD1; pW = nW1;

        // slide target window, load sT[j0] (sentinel-padded, no clamp)
        const int j0 = k - i0;
        int u = j0 + PADF;
        int ii = u + (u >> 2);
#pragma unroll
        for (int q = RR - 1; q >= 1; --q) { tx[q] = tx[q - 1]; ty[q] = ty[q - 1]; }
        tx[0] = sTx[ii]; ty[0] = sTy[ii];

#pragma unroll
        for (int rr = RR - 1; rr >= 0; --rr) {
            float up, dg, wu, wd;
            if (rr == 0) { up = nD1; dg = nD2; wu = nW1; wd = nW2; }
            else         { up = D1[rr - 1]; dg = D2[rr - 1]; wu = W1[rr - 1]; wd = W2[rr - 1]; }
            const float lf = D1[rr];
            const float wl = W1[rr];

            const float dx = px[rr] - tx[rr];
            const float dy = py[rr] - ty[rr];
            const float c  = fsqrt_approx(dx * dx + dy * dy);
            const float w  = fabsf(dx) * s0 + fabsf(dy) * s1;

            const float best = fminf(fminf(dg, up), lf);
            // first-min-wins over [diag, up, left] (matches jnp.argmin)
            float ws = (up <= lf) ? wu : wl;
            ws = ((dg <= up) && (dg <= lf)) ? wd : ws;

            D2[rr] = D1[rr]; D1[rr] = c + best;
            W2[rr] = W1[rr]; W1[rr] = w + ws;
        }

        // boundary publish; counter release once per chunk (+ at the end)
        if (warp < NWARP - 1 && lane == 31) {
            ring[warp * RING + k] = make_float2(D1[RR - 1], W1[RR - 1]);
            if ((rel & (SCH - 1)) == (SCH - 1) || k == kend) {
                asm volatile("st.release.cta.shared.u32 [%0], %1;"
                             :: "r"(myCnt), "r"((unsigned)(k + 1)) : "memory");
            }
        }
    }

    if (tid == TT - 1)                 // row N-1: W1[RR-1] == W[N-1][M-1]
        g_partial[b] = W1[RR - 1];
}

__global__ void dtw_reduce_kernel(float* __restrict__ out, int B)
{
    int l = threadIdx.x;
    float s = 0.f;
    if (l < B)      s += g_partial[l];
    if (l + 32 < B) s += g_partial[l + 32];
#pragma unroll
    for (int o = 16; o; o >>= 1) s += __shfl_xor_sync(0xffffffffu, s, o);
    if (l == 0) out[0] = s;
}

extern "C" void kernel_launch(void* const* d_in, const int* in_sizes, int n_in,
                              void* d_out, int out_size)
{
    const float* preds   = (const float*)d_in[0];
    const float* targs   = (const float*)d_in[1];
    const float* subcoef = (const float*)d_in[2];
    float* out = (float*)d_out;

    int B = in_sizes[0] / (NN * 4);
    if (B < 1) B = 1;
    if (B > 64) B = 64;

    cudaFuncSetAttribute(dtw_forward_kernel,
                         cudaFuncAttributeMaxDynamicSharedMemorySize, SMEM_BYTES);

    dtw_forward_kernel<<<B, TT, SMEM_BYTES>>>(preds, targs, subcoef);
    dtw_reduce_kernel<<<1, 32>>>(out, B);
}

// round 6
// speedup vs baseline: 1.0662x; 1.0662x over previous
#include <cuda_runtime.h>

// DTW loss: 32 independent 1024x1024 wavefront DPs, fused with path-loss
// accumulation (W[i,j] = w(i,j) + W[argmin-pred]) -> no backtrack needed.
//
// R5: each DP split across a 2-CTA cluster (rows 0-511 / 512-1023) -> 64
// clusters, 128 SMs busy. Per CTA: 8 warps x RR=2 (2 warps/SMSP for latency
// hiding). Warp-to-warp handoff = chunked release/acquire ring; the single
// cross-CTA boundary uses the SAME protocol through DSMEM (producer does
// remote weak stores + remote release counter; consumer polls its own smem).

#define NN 1024
#define MM 1024
#define RR 2                 // rows per thread
#define TT 256               // threads per CTA
#define NWARP 8              // warps per CTA
#define CLUSTER 2
#define GWARPS (NWARP * CLUSTER)
#define BAND 64              // rows per warp
#define HALFROWS 512
#define RING 2048
#define SCH 16               // diagonals per sync chunk

#define FINF (__int_as_float(0x7f800000))
#define SENT 1.0e18f

__device__ float g_partial[64];

static __forceinline__ __device__ float fsqrt_approx(float x) {
    float r;
    asm("sqrt.approx.f32 %0, %1;" : "=f"(r) : "f"(x));
    return r;
}
static __forceinline__ __device__ unsigned smem_u32(const void* p) {
    return (unsigned)__cvta_generic_to_shared(p);
}

// target array: logical j in [-PADF, MM-1+PADF], swizzled idx = u + u/4
#define PADF 64
#define STN  1472
#define NRING 8              // slots 0..6 local producers, slot 7 incoming DSMEM
#define SMEM_BYTES (NRING * RING * 8 + 2 * STN * 4 + 32)

__global__ void __launch_bounds__(TT, 1) __cluster_dims__(CLUSTER, 1, 1)
dtw_forward_kernel(const float* __restrict__ preds,
                   const float* __restrict__ targs,
                   const float* __restrict__ subcoef)
{
    extern __shared__ unsigned char smem_raw[];
    float2*   ring = (float2*)smem_raw;               // [NRING][RING]
    float*    sTx  = (float*)(ring + NRING * RING);   // [STN] swizzled + padded
    float*    sTy  = sTx + STN;
    unsigned* cnt  = (unsigned*)(sTy + STN);          // [8] progress counters

    const int half = blockIdx.x & 1;                  // cluster rank
    const int b    = blockIdx.x >> 1;                 // batch
    const int tid  = threadIdx.x;
    const int lane = tid & 31;
    const int warp = tid >> 5;
    const int g    = half * NWARP + warp;             // global warp 0..15

    const float* __restrict__ pb = preds + (size_t)b * NN * 4;
    const float* __restrict__ tb = targs + (size_t)b * MM * 4;

    // stage targets with sentinel pad; swizzle idx = u + u/4
    for (int u = tid; u < PADF + MM + PADF + 1; u += TT) {
        int j = u - PADF;
        int idx = u + (u >> 2);
        bool in = (unsigned)j < (unsigned)MM;
        int jc = in ? j : 0;
        sTx[idx] = in ? tb[jc * 4 + 0] : SENT;
        sTy[idx] = in ? tb[jc * 4 + 1] : SENT;
    }
    if (tid < NRING) cnt[tid] = 0;

    const float s0 = subcoef[0];
    const float s1 = subcoef[1];

    const int i0g = half * HALFROWS + tid * RR;       // global first row
    float px[RR], py[RR];
#pragma unroll
    for (int r = 0; r < RR; ++r) {
        px[r] = pb[(i0g + r) * 4 + 0];
        py[r] = pb[(i0g + r) * 4 + 1];
    }

    float D1[RR], D2[RR], W1[RR], W2[RR];
#pragma unroll
    for (int r = 0; r < RR; ++r) { D1[r] = FINF; D2[r] = FINF; W1[r] = 0.f; W2[r] = 0.f; }

    // diag-(k-2) neighbor-row cache; global warp0/lane0 seeds 0 for cell (0,0)
    float pD = (g == 0 && lane == 0) ? 0.f : FINF;
    float pW = 0.f;

    // producer: warp w writes ring[w]/cnt[w]; CTA0 warp7 writes into CTA1's
    // slot 7 via mapa'd cluster-shared addresses (unified store path).
    const bool produce = (g < GWARPS - 1);
    const int  dstRank = (warp == NWARP - 1) ? (half + 1) : half;
    unsigned ring_st = 0, cnt_st = 0;
    {
        unsigned rl = smem_u32(&ring[warp * RING]);
        unsigned cl = smem_u32(&cnt[warp]);
        asm("mapa.shared::cluster.u32 %0, %1, %2;" : "=r"(ring_st) : "r"(rl), "r"(dstRank));
        asm("mapa.shared::cluster.u32 %0, %1, %2;" : "=r"(cnt_st)  : "r"(cl), "r"(dstRank));
    }
    // consumer: warp w reads ring[w-1]; CTA1 warp0 reads incoming slot 7
    const int srcIdx = (warp == 0) ? 7 : (warp - 1);
    const float2*  srcRing = &ring[srcIdx * RING];
    const unsigned prevCnt = smem_u32(&cnt[srcIdx]);

    // cluster-wide sync: counters/targets initialized in BOTH CTAs before any
    // remote store can land
    asm volatile("barrier.cluster.arrive.aligned;" ::: "memory");
    asm volatile("barrier.cluster.wait.aligned;" ::: "memory");

    const int kstart  = g * BAND;
    const int kend    = kstart + BAND - 1 + MM - 1;
    const int pollend = kstart + MM - 1;

    // chunk-0 poll (uniform) + peel of srcRing[kstart-2] for pD
    if (g > 0) {
        int need = kstart + SCH - 1;
        if (need > pollend) need = pollend;
        unsigned c;
        asm volatile("ld.acquire.cluster.shared.u32 %0, [%1];" : "=r"(c) : "r"(prevCnt));
        while ((int)c < need) {
            __nanosleep(64);
            asm volatile("ld.acquire.cluster.shared.u32 %0, [%1];" : "=r"(c) : "r"(prevCnt));
        }
        if (lane == 0) {
            float2 e = srcRing[kstart - 2];
            pD = e.x; pW = e.y;
        }
    }

    // sliding target window: after the in-loop shift, tx[rr] = sT[j0 - rr]
    const int j0f = kstart - i0g;
    float tx[RR], ty[RR];
    {
        int u = j0f - 1 + PADF;
        int ii = u + (u >> 2);
        tx[0] = sTx[ii]; ty[0] = sTy[ii];
        tx[1] = SENT;    ty[1] = SENT;
    }

#pragma unroll 4
    for (int k = kstart; k <= kend; ++k) {
        const int rel = k - kstart;

        // per-chunk acquire poll (uniform, nanosleep backoff)
        if (g > 0 && rel != 0 && (rel & (SCH - 1)) == 0 && k <= pollend) {
            int need = k + SCH - 1;
            if (need > pollend) need = pollend;
            unsigned c;
            asm volatile("ld.acquire.cluster.shared.u32 %0, [%1];" : "=r"(c) : "r"(prevCnt));
            while ((int)c < need) {
                __nanosleep(64);
                asm volatile("ld.acquire.cluster.shared.u32 %0, [%1];" : "=r"(c) : "r"(prevCnt));
            }
        }

        float nD1 = __shfl_up_sync(0xffffffffu, D1[RR - 1], 1);
        float nW1 = __shfl_up_sync(0xffffffffu, W1[RR - 1], 1);
        if (lane == 0) {
            if (g == 0 || k > pollend) {
                nD1 = FINF; nW1 = 0.f;
            } else {
                float2 e = srcRing[k - 1];
                nD1 = e.x; nW1 = e.y;
            }
        }
        const float nD2 = pD, nW2 = pW;
        pD = nD1; pW = nW1;

        // slide target window, load sT[j0] (sentinel-padded, no clamp)
        const int j0 = k - i0g;
        int u = j0 + PADF;
        int ii = u + (u >> 2);
        tx[1] = tx[0]; ty[1] = ty[0];
        tx[0] = sTx[ii]; ty[0] = sTy[ii];

#pragma unroll
        for (int rr = RR - 1; rr >= 0; --rr) {
            float up, dg, wu, wd;
            if (rr == 0) { up = nD1; dg = nD2; wu = nW1; wd = nW2; }
            else         { up = D1[rr - 1]; dg = D2[rr - 1]; wu = W1[rr - 1]; wd = W2[rr - 1]; }
            const float lf = D1[rr];
            const float wl = W1[rr];

            const float dx = px[rr] - tx[rr];
            const float dy = py[rr] - ty[rr];
            const float c  = fsqrt_approx(dx * dx + dy * dy);
            const float w  = fabsf(dx) * s0 + fabsf(dy) * s1;

            const float best = fminf(fminf(dg, up), lf);
            // first-min-wins over [diag, up, left] (matches jnp.argmin)
            float ws = (up <= lf) ? wu : wl;
            ws = ((dg <= up) && (dg <= lf)) ? wd : ws;

            D2[rr] = D1[rr]; D1[rr] = c + best;
            W2[rr] = W1[rr]; W1[rr] = w + ws;
        }

        // boundary publish (cluster-shared path covers local + remote);
        // counter release once per chunk (+ at the end)
        if (produce && lane == 31) {
            unsigned long long v;
            asm("mov.b64 %0, {%1, %2};" : "=l"(v) : "f"(D1[RR - 1]), "f"(W1[RR - 1]));
            asm volatile("st.weak.shared::cluster.b64 [%0], %1;"
                         :: "r"(ring_st + (unsigned)k * 8u), "l"(v) : "memory");
            if ((rel & (SCH - 1)) == (SCH - 1) || k == kend) {
                asm volatile("st.release.cluster.shared::cluster.u32 [%0], %1;"
                             :: "r"(cnt_st), "r"((unsigned)(k + 1)) : "memory");
            }
        }
    }

    if (half == 1 && tid == TT - 1)    // global row N-1: W1[RR-1] == W[N-1][M-1]
        g_partial[b] = W1[RR - 1];

    // keep cluster smem alive until all remote traffic has landed
    asm volatile("barrier.cluster.arrive.aligned;" ::: "memory");
    asm volatile("barrier.cluster.wait.aligned;" ::: "memory");
}

__global__ void dtw_reduce_kernel(float* __restrict__ out, int B)
{
    int l = threadIdx.x;
    float s = 0.f;
    if (l < B)      s += g_partial[l];
    if (l + 32 < B) s += g_partial[l + 32];
#pragma unroll
    for (int o = 16; o; o >>= 1) s += __shfl_xor_sync(0xffffffffu, s, o);
    if (l == 0) out[0] = s;
}

extern "C" void kernel_launch(void* const* d_in, const int* in_sizes, int n_in,
                              void* d_out, int out_size)
{
    const float* preds   = (const float*)d_in[0];
    const float* targs   = (const float*)d_in[1];
    const float* subcoef = (const float*)d_in[2];
    float* out = (float*)d_out;

    int B = in_sizes[0] / (NN * 4);
    if (B < 1) B = 1;
    if (B > 64) B = 64;

    cudaFuncSetAttribute(dtw_forward_kernel,
                         cudaFuncAttributeMaxDynamicSharedMemorySize, SMEM_BYTES);

    dtw_forward_kernel<<<2 * B, TT, SMEM_BYTES>>>(preds, targs, subcoef);
    dtw_reduce_kernel<<<1, 32>>>(out, B);
}

// round 8
// speedup vs baseline: 1.8415x; 1.7271x over previous
#include <cuda_runtime.h>

// DTW loss: 32 independent 1024x1024 wavefront DPs, fused with path-loss
// accumulation (W[i,j] = w(i,j) + W[argmin-pred]) -> no backtrack needed.
//
// R7: R6 (branch-free hot loop) with the producer ring-slot addressing bug
// fixed (publish went to &ring[warp] instead of &ring[warp*RING]).
//  - ring read = broadcast LDS by all lanes + select merge (no divergent if)
//  - publish   = predicated @p st.shared (inline asm, no BSSY/BSYNC)
//  - chunk structure hoisted: Phase A (32 chunks x 32 steps, poll per chunk),
//    Phase B (127 steps, neighbor statically FINF) -> zero per-step branches.

#define NN 1024
#define MM 1024
#define RR 4                 // rows per thread
#define TT 256               // threads per block
#define NWARP 8
#define BAND 128             // rows per warp
#define RING 2048
#define SCH 32               // diagonals per sync chunk

#define FINF (__int_as_float(0x7f800000))
#define SENT 1.0e18f

__device__ float g_partial[64];

static __forceinline__ __device__ float fsqrt_approx(float x) {
    float r;
    asm("sqrt.approx.f32 %0, %1;" : "=f"(r) : "f"(x));
    return r;
}
static __forceinline__ __device__ unsigned smem_u32(const void* p) {
    return (unsigned)__cvta_generic_to_shared(p);
}

// target array: logical j in [-PADF, MM-1+PADF], swizzled idx = u + u/4
#define PADF 127
#define STN  1600
#define RING_F2 (7 * RING)
#define SMEM_BYTES (RING_F2 * 8 + 2 * STN * 4 + 8 * 4)

__global__ void __launch_bounds__(TT, 1)
dtw_forward_kernel(const float* __restrict__ preds,
                   const float* __restrict__ targs,
                   const float* __restrict__ subcoef)
{
    extern __shared__ unsigned char smem_raw[];
    float2*   ring = (float2*)smem_raw;               // [7][RING]
    float*    sTx  = (float*)(ring + RING_F2);        // [STN] swizzled + padded
    float*    sTy  = sTx + STN;
    unsigned* cnt  = (unsigned*)(sTy + STN);          // [8] progress counters

    const int b    = blockIdx.x;
    const int tid  = threadIdx.x;
    const int lane = tid & 31;
    const int warp = tid >> 5;

    const float* __restrict__ pb = preds + (size_t)b * NN * 4;
    const float* __restrict__ tb = targs + (size_t)b * MM * 4;

    // stage targets with sentinel pad; swizzle idx = u + u/4 (stride-5 words
    // -> conflict-free for the stride-4 lane access pattern)
    for (int u = tid; u < PADF + MM + PADF + 1; u += TT) {
        int j = u - PADF;
        int idx = u + (u >> 2);
        bool in = (unsigned)j < (unsigned)MM;
        int jc = in ? j : 0;
        sTx[idx] = in ? tb[jc * 4 + 0] : SENT;
        sTy[idx] = in ? tb[jc * 4 + 1] : SENT;
    }
    if (tid < NWARP) cnt[tid] = 0;

    const float s0 = subcoef[0];
    const float s1 = subcoef[1];

    const int i0 = tid * RR;
    float px[RR], py[RR];
#pragma unroll
    for (int r = 0; r < RR; ++r) {
        px[r] = pb[(i0 + r) * 4 + 0];
        py[r] = pb[(i0 + r) * 4 + 1];
    }

    float D1[RR], D2[RR], W1[RR], W2[RR];
#pragma unroll
    for (int r = 0; r < RR; ++r) { D1[r] = FINF; D2[r] = FINF; W1[r] = 0.f; W2[r] = 0.f; }

    // diag-(k-2) neighbor-row cache; warp0/lane0 seeds 0 for cell (0,0)
    float pD = (warp == 0 && lane == 0) ? 0.f : FINF;
    float pW = 0.f;

    const bool     lane0   = (lane == 0);
    const bool     ringOn  = (warp != 0);                 // uniform per warp
    const unsigned pubFlag = (warp < NWARP - 1 && lane == 31) ? 1u : 0u;
    const unsigned myCnt   = smem_u32(&cnt[warp]);
    const unsigned prevCnt = smem_u32(&cnt[warp > 0 ? warp - 1 : 0]);
    const float2*  srcRing = &ring[(warp > 0 ? warp - 1 : 0) * RING];
    // producer warp w writes slot w (clamped in-bounds for warp 7, whose
    // store is predicated off via pubFlag=0)
    const unsigned pubRing = smem_u32(&ring[(warp < NWARP - 1 ? warp : 0) * RING]);

    __syncthreads();

    const int kstart = warp * BAND;

    // chunk-0 poll (uniform) + peel of srcRing[kstart-2] for pD
    if (ringOn) {
        const int need = kstart + SCH - 1;
        unsigned c;
        asm volatile("ld.acquire.cta.shared.u32 %0, [%1];" : "=r"(c) : "r"(prevCnt));
        while ((int)c < need) {
            __nanosleep(64);
            asm volatile("ld.acquire.cta.shared.u32 %0, [%1];" : "=r"(c) : "r"(prevCnt));
        }
        if (lane0) {
            float2 e = srcRing[kstart - 2];
            pD = e.x; pW = e.y;
        }
    }

    // sliding target window: after the in-loop shift, tx[rr] = sT[j0 - rr]
    const int j0f = kstart - i0;
    float tx[RR], ty[RR];
#pragma unroll
    for (int q = 0; q < RR - 1; ++q) {
        int u = j0f - 1 - q + PADF;
        int ii = u + (u >> 2);
        tx[q] = sTx[ii]; ty[q] = sTy[ii];
    }
    tx[RR - 1] = SENT; ty[RR - 1] = SENT;

    // ---- branch-free step body -------------------------------------------
#define DTW_STEP(KK, USE_RING) do {                                          \
    const int k_ = (KK);                                                     \
    float nD1 = __shfl_up_sync(0xffffffffu, D1[RR - 1], 1);                  \
    float nW1 = __shfl_up_sync(0xffffffffu, W1[RR - 1], 1);                  \
    if (USE_RING) {                                                          \
        float2 e_ = srcRing[(k_ - 1) & (RING - 1)];  /* broadcast LDS */     \
        float rD_ = ringOn ? e_.x : FINF;                                    \
        float rW_ = ringOn ? e_.y : 0.f;                                     \
        nD1 = lane0 ? rD_ : nD1;                                             \
        nW1 = lane0 ? rW_ : nW1;                                             \
    } else {                                                                 \
        nD1 = lane0 ? FINF : nD1;                                            \
        nW1 = lane0 ? 0.f  : nW1;                                            \
    }                                                                        \
    const float nD2 = pD, nW2 = pW;                                          \
    pD = nD1; pW = nW1;                                                      \
    {   /* slide target window, load sT[j0] */                               \
        const int j0_ = k_ - i0;                                             \
        int u_ = j0_ + PADF;                                                 \
        int ii_ = u_ + (u_ >> 2);                                            \
        tx[3] = tx[2]; ty[3] = ty[2];                                        \
        tx[2] = tx[1]; ty[2] = ty[1];                                        \
        tx[1] = tx[0]; ty[1] = ty[0];                                        \
        tx[0] = sTx[ii_]; ty[0] = sTy[ii_];                                  \
    }                                                                        \
    _Pragma("unroll")                                                        \
    for (int rr = RR - 1; rr >= 0; --rr) {                                   \
        float up, dg, wu, wd;                                                \
        if (rr == 0) { up = nD1; dg = nD2; wu = nW1; wd = nW2; }             \
        else         { up = D1[rr - 1]; dg = D2[rr - 1];                     \
                       wu = W1[rr - 1]; wd = W2[rr - 1]; }                   \
        const float lf = D1[rr];                                             \
        const float wl = W1[rr];                                             \
        const float dx = px[rr] - tx[rr];                                    \
        const float dy = py[rr] - ty[rr];                                    \
        const float c_ = fsqrt_approx(dx * dx + dy * dy);                    \
        const float w_ = fabsf(dx) * s0 + fabsf(dy) * s1;                    \
        const float best = fminf(fminf(dg, up), lf);                         \
        float ws = (up <= lf) ? wu : wl;   /* first-min-wins [dg,up,lf] */   \
        ws = ((dg <= up) && (dg <= lf)) ? wd : ws;                           \
        D2[rr] = D1[rr]; D1[rr] = c_ + best;                                 \
        W2[rr] = W1[rr]; W1[rr] = w_ + ws;                                   \
    }                                                                        \
    /* predicated publish: no divergent branch */                            \
    asm volatile("{\n\t.reg .pred p;\n\tsetp.ne.u32 p, %0, 0;\n\t"           \
                 "@p st.shared.v2.f32 [%1], {%2, %3};\n\t}"                  \
                 :: "r"(pubFlag), "r"(pubRing + (unsigned)(k_ * 8)),         \
                    "f"(D1[RR - 1]), "f"(W1[RR - 1]) : "memory");            \
} while (0)

#define DTW_RELEASE(VAL) do {                                                \
    asm volatile("{\n\t.reg .pred p;\n\tsetp.ne.u32 p, %0, 0;\n\t"           \
                 "@p st.release.cta.shared.u32 [%1], %2;\n\t}"               \
                 :: "r"(pubFlag), "r"(myCnt), "r"((unsigned)(VAL))           \
                 : "memory");                                                \
} while (0)
    // ----------------------------------------------------------------------

    // Phase A: 32 chunks x SCH steps, ring-fed (k in [kstart, kstart+1024))
    for (int c = 0; c < 32; ++c) {
        const int kbase = kstart + c * SCH;
        if (ringOn & (c != 0)) {                      // uniform poll per chunk
            const int need = kbase + SCH - 1;
            unsigned cv;
            asm volatile("ld.acquire.cta.shared.u32 %0, [%1];" : "=r"(cv) : "r"(prevCnt));
            while ((int)cv < need) {
                __nanosleep(64);
                asm volatile("ld.acquire.cta.shared.u32 %0, [%1];" : "=r"(cv) : "r"(prevCnt));
            }
        }
#pragma unroll 4
        for (int s = 0; s < SCH; ++s) DTW_STEP(kbase + s, true);
        DTW_RELEASE(kbase + SCH);
    }

    // Phase B: 127 steps, neighbor statically FINF (k in [kstart+1024, kend])
    for (int c = 0; c < 4; ++c) {
        const int kbase = kstart + 1024 + c * SCH;
        const int lim   = (c == 3) ? (SCH - 1) : SCH;
#pragma unroll 4
        for (int s = 0; s < lim; ++s) DTW_STEP(kbase + s, false);
        DTW_RELEASE(kbase + lim);
    }

    if (tid == TT - 1)                 // row N-1: W1[RR-1] == W[N-1][M-1]
        g_partial[b] = W1[RR - 1];
}

__global__ void dtw_reduce_kernel(float* __restrict__ out, int B)
{
    int l = threadIdx.x;
    float s = 0.f;
    if (l < B)      s += g_partial[l];
    if (l + 32 < B) s += g_partial[l + 32];
#pragma unroll
    for (int o = 16; o; o >>= 1) s += __shfl_xor_sync(0xffffffffu, s, o);
    if (l == 0) out[0] = s;
}

extern "C" void kernel_launch(void* const* d_in, const int* in_sizes, int n_in,
                              void* d_out, int out_size)
{
    const float* preds   = (const float*)d_in[0];
    const float* targs   = (const float*)d_in[1];
    const float* subcoef = (const float*)d_in[2];
    float* out = (float*)d_out;

    int B = in_sizes[0] / (NN * 4);
    if (B < 1) B = 1;
    if (B > 64) B = 64;

    cudaFuncSetAttribute(dtw_forward_kernel,
                         cudaFuncAttributeMaxDynamicSharedMemorySize, SMEM_BYTES);

    dtw_forward_kernel<<<B, TT, SMEM_BYTES>>>(preds, targs, subcoef);
    dtw_reduce_kernel<<<1, 32>>>(out, B);
}